// round 11
// baseline (speedup 1.0000x reference)
#include <cuda_runtime.h>
#include <cstdint>

#define QP_THREADS   512
#define QP_TILE_F4   1024                 // float4 per tile = 16KB
#define QP_TILE_B    (QP_TILE_F4 * 16)    // 16384 bytes
#define QP_STAGES    7
#define QP_SMEM_SIZE (QP_STAGES * QP_TILE_B + QP_STAGES * 8)

// ---- PTX helpers ----
__device__ __forceinline__ uint32_t smem_u32(const void* p) {
    uint32_t a;
    asm("{ .reg .u64 t; cvta.to.shared.u64 t, %1; cvt.u32.u64 %0, t; }"
        : "=r"(a) : "l"(p));
    return a;
}
__device__ __forceinline__ void mbar_init(uint32_t mb, uint32_t cnt) {
    asm volatile("mbarrier.init.shared.b64 [%0], %1;" :: "r"(mb), "r"(cnt) : "memory");
}
__device__ __forceinline__ void mbar_expect_tx(uint32_t mb, uint32_t bytes) {
    asm volatile("mbarrier.arrive.expect_tx.shared.b64 _, [%0], %1;"
                 :: "r"(mb), "r"(bytes) : "memory");
}
__device__ __forceinline__ void mbar_wait(uint32_t mb, uint32_t parity) {
    uint32_t done;
    asm volatile(
        "{\n\t.reg .pred p;\n\t"
        "mbarrier.try_wait.parity.acquire.cta.shared::cta.b64 p, [%1], %2;\n\t"
        "selp.b32 %0, 1, 0, p;\n\t}"
        : "=r"(done) : "r"(mb), "r"(parity) : "memory");
    if (!done) {
        asm volatile(
            "{\n\t.reg .pred P1;\n\t"
            "WAIT_LOOP_%=:\n\t"
            "mbarrier.try_wait.parity.acquire.cta.shared::cta.b64 P1, [%0], %1, 0x989680;\n\t"
            "@P1 bra.uni WAIT_DONE_%=;\n\t"
            "bra.uni WAIT_LOOP_%=;\n\t"
            "WAIT_DONE_%=:\n\t}"
            :: "r"(mb), "r"(parity) : "memory");
    }
}
// 1D bulk async copy global->shared::cta, completion via mbarrier tx-bytes
__device__ __forceinline__ void cp_bulk_g2s(uint32_t dst, const void* src,
                                            uint32_t bytes, uint32_t mb) {
    asm volatile(
        "cp.async.bulk.shared::cta.global.mbarrier::complete_tx::bytes [%0], [%1], %2, [%3];"
        :: "r"(dst), "l"(src), "r"(bytes), "r"(mb) : "memory");
}

// ---- packed f32x2 FFMA2 helpers ----
__device__ __forceinline__ unsigned long long pack2(float lo, float hi) {
    unsigned long long r;
    asm("mov.b64 %0, {%1, %2};" : "=l"(r) : "f"(lo), "f"(hi));
    return r;
}
__device__ __forceinline__ void unpack2(unsigned long long v, float& lo, float& hi) {
    asm("mov.b64 {%0, %1}, %2;" : "=f"(lo), "=f"(hi) : "l"(v));
}
__device__ __forceinline__ unsigned long long ffma2(unsigned long long a,
                                                    unsigned long long b,
                                                    unsigned long long c) {
    unsigned long long r;
    asm("fma.rn.f32x2 %0, %1, %2, %3;" : "=l"(r) : "l"(a), "l"(b), "l"(c));
    return r;
}

// ---- circuit collapse (MUFU-cheap, per thread) ----
struct C2 { float r, i; };
__device__ __forceinline__ C2 cmul(C2 a, C2 b) {
    return { a.r * b.r - a.i * b.i, a.r * b.i + a.i * b.r };
}
__device__ __forceinline__ C2 cadd(C2 a, C2 b) { return { a.r + b.r, a.i + b.i }; }
__device__ __forceinline__ void mm2(const C2 A[2][2], const C2 B[2][2], C2 O[2][2]) {
#pragma unroll
    for (int r = 0; r < 2; r++)
#pragma unroll
        for (int c = 0; c < 2; c++)
            O[r][c] = cadd(cmul(A[r][0], B[0][c]), cmul(A[r][1], B[1][c]));
}
__device__ __forceinline__ void layer_unitary(float w0, float w1, float w2, C2 U[2][2]) {
    float c0, s0, c1, s1, c2, s2;
    __sincosf(0.5f * w0, &s0, &c0);
    __sincosf(0.5f * w1, &s1, &c1);
    __sincosf(0.5f * w2, &s2, &c2);
    C2 rx[2][2] = { { {c0, 0.f}, {0.f, -s0} }, { {0.f, -s0}, {c0, 0.f} } };
    C2 ry[2][2] = { { {c1, 0.f}, {-s1, 0.f} }, { {s1, 0.f}, {c1, 0.f} } };
    C2 rz[2][2] = { { {c2, -s2}, {0.f, 0.f} }, { {0.f, 0.f}, {c2, s2} } };
    C2 t[2][2];
    mm2(ry, rx, t);
    mm2(rz, t, U);
}
__device__ __forceinline__ void compute_coefs(const float* __restrict__ weights,
                                              const float* __restrict__ a,
                                              const float* __restrict__ b,
                                              float& ca, float& cb, float& bb) {
    C2 U0[2][2], U1[2][2], U[2][2];
    layer_unitary(__ldg(weights + 0), __ldg(weights + 1), __ldg(weights + 2), U0);
    layer_unitary(__ldg(weights + 3), __ldg(weights + 4), __ldg(weights + 5), U1);
    mm2(U1, U0, U);
    float alpha = (U[0][0].r * U[0][0].r + U[0][0].i * U[0][0].i)
                - (U[1][0].r * U[1][0].r + U[1][0].i * U[1][0].i);
    float beta  = (U[0][0].r * U[0][1].r + U[0][0].i * U[0][1].i)
                - (U[1][0].r * U[1][1].r + U[1][0].i * U[1][1].i);
    float av = __ldg(a);
    ca = av * alpha;
    cb = av * beta;
    bb = __ldg(b);
}
__device__ __forceinline__ float4 eval4(float4 v, unsigned long long ca2,
                                        unsigned long long cb2, unsigned long long bb2) {
    float sx, cx, sy, cy, sz, cz, sw, cw;
    __sincosf(v.x, &sx, &cx);
    __sincosf(v.y, &sy, &cy);
    __sincosf(v.z, &sz, &cz);
    __sincosf(v.w, &sw, &cw);
    unsigned long long r01 = ffma2(ca2, pack2(cx, cy), ffma2(cb2, pack2(sx, sy), bb2));
    unsigned long long r23 = ffma2(ca2, pack2(cz, cw), ffma2(cb2, pack2(sz, sw), bb2));
    float4 o;
    unpack2(r01, o.x, o.y);
    unpack2(r23, o.z, o.w);
    return o;
}

__global__ void __launch_bounds__(QP_THREADS)
qpinn_tma(const float* __restrict__ x, float* __restrict__ out, int ntiles, int n,
          const float* __restrict__ weights,
          const float* __restrict__ a, const float* __restrict__ b) {
    extern __shared__ __align__(128) unsigned char smem_raw[];

    float ca, cb, bb;
    compute_coefs(weights, a, b, ca, cb, bb);
    const unsigned long long ca2 = pack2(ca, ca);
    const unsigned long long cb2 = pack2(cb, cb);
    const unsigned long long bb2 = pack2(bb, bb);

    const int tid = threadIdx.x;
    const uint32_t smem_base = smem_u32(smem_raw);
    const uint32_t data_base = smem_base;
    const uint32_t mbar_base = smem_base + QP_STAGES * QP_TILE_B;

    if (tid == 0) {
#pragma unroll
        for (int s = 0; s < QP_STAGES; s++) mbar_init(mbar_base + 8 * s, 1);
    }
    __syncthreads();

    // Prologue: fill pipeline for this block's first tiles (block-cyclic tiles)
    if (tid == 0) {
        int issued = 0;
        for (long long t = blockIdx.x; t < ntiles && issued < QP_STAGES;
             t += gridDim.x, issued++) {
            uint32_t mb = mbar_base + 8 * issued;
            mbar_expect_tx(mb, QP_TILE_B);
            cp_bulk_g2s(data_base + issued * QP_TILE_B,
                        x + t * (QP_TILE_F4 * 4), QP_TILE_B, mb);
        }
    }

    float4* __restrict__ out4 = (float4*)out;
    int stage = 0, phase = 0;
    for (long long t = blockIdx.x; t < ntiles; t += gridDim.x) {
        mbar_wait(mbar_base + 8 * stage, phase);

        const float4* src = (const float4*)(smem_raw + stage * QP_TILE_B);
        float4* dst = out4 + t * QP_TILE_F4;
#pragma unroll
        for (int k = 0; k < QP_TILE_F4 / QP_THREADS; k++) {   // 2 float4 per thread
            float4 v = src[tid + k * QP_THREADS];             // conflict-free LDS.128
            __stcs(dst + tid + k * QP_THREADS, eval4(v, ca2, cb2, bb2));
        }
        __syncthreads();  // all consumers done with this stage before refill

        long long tn = t + (long long)QP_STAGES * gridDim.x;
        if (tid == 0 && tn < ntiles) {
            uint32_t mb = mbar_base + 8 * stage;
            mbar_expect_tx(mb, QP_TILE_B);
            cp_bulk_g2s(data_base + stage * QP_TILE_B,
                        x + tn * (QP_TILE_F4 * 4), QP_TILE_B, mb);
        }
        if (++stage == QP_STAGES) { stage = 0; phase ^= 1; }
    }

    // Remainder elements (n not a multiple of tile size) — simple grid-stride
    long long rem_start = (long long)ntiles * (QP_TILE_F4 * 4);
    for (long long i = rem_start + (long long)blockIdx.x * QP_THREADS + tid;
         i < n; i += (long long)gridDim.x * QP_THREADS) {
        float s, c;
        __sincosf(__ldcs(x + i), &s, &c);
        float caf, cbf, bbf, dum;
        unpack2(ca2, caf, dum); unpack2(cb2, cbf, dum); unpack2(bb2, bbf, dum);
        __stcs(out + i, fmaf(caf, c, fmaf(cbf, s, bbf)));
    }
}

extern "C" void kernel_launch(void* const* d_in, const int* in_sizes, int n_in,
                              void* d_out, int out_size) {
    const float* x       = (const float*)d_in[0];
    const float* weights = (const float*)d_in[1];
    const float* a       = (const float*)d_in[2];
    const float* b       = (const float*)d_in[3];
    float* out = (float*)d_out;

    int n = in_sizes[0];
    int ntiles = n / (QP_TILE_F4 * 4);   // 4096-float tiles

    cudaFuncSetAttribute(qpinn_tma, cudaFuncAttributeMaxDynamicSharedMemorySize,
                         QP_SMEM_SIZE);

    // 2 CTAs/SM (112KB smem each -> 224KB/SM), single persistent wave.
    int blocks = 148 * 2;
    if (ntiles > 0 && ntiles < blocks) blocks = ntiles;
    if (ntiles == 0) blocks = 1;

    qpinn_tma<<<blocks, QP_THREADS, QP_SMEM_SIZE>>>(x, out, ntiles, n,
                                                    weights, a, b);
}

// round 12
// speedup vs baseline: 1.1018x; 1.1018x over previous
#include <cuda_runtime.h>
#include <cstdint>

#define QP_THREADS   256
#define QP_TILE_F4   1024                 // float4 per tile = 16KB
#define QP_TILE_B    (QP_TILE_F4 * 16)    // 16384 bytes
#define QP_STAGES    4
#define QP_SMEM_SIZE (QP_STAGES * QP_TILE_B + QP_STAGES * 8)   // 64KB + barriers

// ---- PTX helpers ----
__device__ __forceinline__ uint32_t smem_u32(const void* p) {
    uint32_t a;
    asm("{ .reg .u64 t; cvta.to.shared.u64 t, %1; cvt.u32.u64 %0, t; }"
        : "=r"(a) : "l"(p));
    return a;
}
__device__ __forceinline__ void mbar_init(uint32_t mb, uint32_t cnt) {
    asm volatile("mbarrier.init.shared.b64 [%0], %1;" :: "r"(mb), "r"(cnt) : "memory");
}
__device__ __forceinline__ void mbar_expect_tx(uint32_t mb, uint32_t bytes) {
    asm volatile("mbarrier.arrive.expect_tx.shared.b64 _, [%0], %1;"
                 :: "r"(mb), "r"(bytes) : "memory");
}
__device__ __forceinline__ void mbar_wait(uint32_t mb, uint32_t parity) {
    uint32_t done;
    asm volatile(
        "{\n\t.reg .pred p;\n\t"
        "mbarrier.try_wait.parity.acquire.cta.shared::cta.b64 p, [%1], %2;\n\t"
        "selp.b32 %0, 1, 0, p;\n\t}"
        : "=r"(done) : "r"(mb), "r"(parity) : "memory");
    if (!done) {
        asm volatile(
            "{\n\t.reg .pred P1;\n\t"
            "WAIT_LOOP_%=:\n\t"
            "mbarrier.try_wait.parity.acquire.cta.shared::cta.b64 P1, [%0], %1, 0x989680;\n\t"
            "@P1 bra.uni WAIT_DONE_%=;\n\t"
            "bra.uni WAIT_LOOP_%=;\n\t"
            "WAIT_DONE_%=:\n\t}"
            :: "r"(mb), "r"(parity) : "memory");
    }
}
// 1D bulk async copy global->shared::cta, completion via mbarrier tx-bytes
__device__ __forceinline__ void cp_bulk_g2s(uint32_t dst, const void* src,
                                            uint32_t bytes, uint32_t mb) {
    asm volatile(
        "cp.async.bulk.shared::cta.global.mbarrier::complete_tx::bytes [%0], [%1], %2, [%3];"
        :: "r"(dst), "l"(src), "r"(bytes), "r"(mb) : "memory");
}

// ---- packed f32x2 FFMA2 helpers ----
__device__ __forceinline__ unsigned long long pack2(float lo, float hi) {
    unsigned long long r;
    asm("mov.b64 %0, {%1, %2};" : "=l"(r) : "f"(lo), "f"(hi));
    return r;
}
__device__ __forceinline__ void unpack2(unsigned long long v, float& lo, float& hi) {
    asm("mov.b64 {%0, %1}, %2;" : "=f"(lo), "=f"(hi) : "l"(v));
}
__device__ __forceinline__ unsigned long long ffma2(unsigned long long a,
                                                    unsigned long long b,
                                                    unsigned long long c) {
    unsigned long long r;
    asm("fma.rn.f32x2 %0, %1, %2, %3;" : "=l"(r) : "l"(a), "l"(b), "l"(c));
    return r;
}

// ---- circuit collapse (MUFU-cheap, per thread) ----
struct C2 { float r, i; };
__device__ __forceinline__ C2 cmul(C2 a, C2 b) {
    return { a.r * b.r - a.i * b.i, a.r * b.i + a.i * b.r };
}
__device__ __forceinline__ C2 cadd(C2 a, C2 b) { return { a.r + b.r, a.i + b.i }; }
__device__ __forceinline__ void mm2(const C2 A[2][2], const C2 B[2][2], C2 O[2][2]) {
#pragma unroll
    for (int r = 0; r < 2; r++)
#pragma unroll
        for (int c = 0; c < 2; c++)
            O[r][c] = cadd(cmul(A[r][0], B[0][c]), cmul(A[r][1], B[1][c]));
}
__device__ __forceinline__ void layer_unitary(float w0, float w1, float w2, C2 U[2][2]) {
    float c0, s0, c1, s1, c2, s2;
    __sincosf(0.5f * w0, &s0, &c0);
    __sincosf(0.5f * w1, &s1, &c1);
    __sincosf(0.5f * w2, &s2, &c2);
    C2 rx[2][2] = { { {c0, 0.f}, {0.f, -s0} }, { {0.f, -s0}, {c0, 0.f} } };
    C2 ry[2][2] = { { {c1, 0.f}, {-s1, 0.f} }, { {s1, 0.f}, {c1, 0.f} } };
    C2 rz[2][2] = { { {c2, -s2}, {0.f, 0.f} }, { {0.f, 0.f}, {c2, s2} } };
    C2 t[2][2];
    mm2(ry, rx, t);
    mm2(rz, t, U);
}
__device__ __forceinline__ void compute_coefs(const float* __restrict__ weights,
                                              const float* __restrict__ a,
                                              const float* __restrict__ b,
                                              float& ca, float& cb, float& bb) {
    C2 U0[2][2], U1[2][2], U[2][2];
    layer_unitary(__ldg(weights + 0), __ldg(weights + 1), __ldg(weights + 2), U0);
    layer_unitary(__ldg(weights + 3), __ldg(weights + 4), __ldg(weights + 5), U1);
    mm2(U1, U0, U);
    float alpha = (U[0][0].r * U[0][0].r + U[0][0].i * U[0][0].i)
                - (U[1][0].r * U[1][0].r + U[1][0].i * U[1][0].i);
    float beta  = (U[0][0].r * U[0][1].r + U[0][0].i * U[0][1].i)
                - (U[1][0].r * U[1][1].r + U[1][0].i * U[1][1].i);
    float av = __ldg(a);
    ca = av * alpha;
    cb = av * beta;
    bb = __ldg(b);
}
__device__ __forceinline__ float4 eval4(float4 v, unsigned long long ca2,
                                        unsigned long long cb2, unsigned long long bb2) {
    float sx, cx, sy, cy, sz, cz, sw, cw;
    __sincosf(v.x, &sx, &cx);
    __sincosf(v.y, &sy, &cy);
    __sincosf(v.z, &sz, &cz);
    __sincosf(v.w, &sw, &cw);
    unsigned long long r01 = ffma2(ca2, pack2(cx, cy), ffma2(cb2, pack2(sx, sy), bb2));
    unsigned long long r23 = ffma2(ca2, pack2(cz, cw), ffma2(cb2, pack2(sz, sw), bb2));
    float4 o;
    unpack2(r01, o.x, o.y);
    unpack2(r23, o.z, o.w);
    return o;
}

__global__ void __launch_bounds__(QP_THREADS, 3)
qpinn_tma(const float* __restrict__ x, float* __restrict__ out, int ntiles, int n,
          const float* __restrict__ weights,
          const float* __restrict__ a, const float* __restrict__ b) {
    extern __shared__ __align__(128) unsigned char smem_raw[];

    float ca, cb, bb;
    compute_coefs(weights, a, b, ca, cb, bb);
    const unsigned long long ca2 = pack2(ca, ca);
    const unsigned long long cb2 = pack2(cb, cb);
    const unsigned long long bb2 = pack2(bb, bb);

    const int tid = threadIdx.x;
    const uint32_t smem_base = smem_u32(smem_raw);
    const uint32_t data_base = smem_base;
    const uint32_t mbar_base = smem_base + QP_STAGES * QP_TILE_B;

    if (tid == 0) {
#pragma unroll
        for (int s = 0; s < QP_STAGES; s++) mbar_init(mbar_base + 8 * s, 1);
    }
    __syncthreads();

    // Prologue: fill pipeline for this block's first tiles (block-cyclic tiles)
    if (tid == 0) {
        int issued = 0;
        for (long long t = blockIdx.x; t < ntiles && issued < QP_STAGES;
             t += gridDim.x, issued++) {
            uint32_t mb = mbar_base + 8 * issued;
            mbar_expect_tx(mb, QP_TILE_B);
            cp_bulk_g2s(data_base + issued * QP_TILE_B,
                        x + t * (QP_TILE_F4 * 4), QP_TILE_B, mb);
        }
    }

    float4* __restrict__ out4 = (float4*)out;
    int stage = 0, phase = 0;
    for (long long t = blockIdx.x; t < ntiles; t += gridDim.x) {
        mbar_wait(mbar_base + 8 * stage, phase);

        const float4* src = (const float4*)(smem_raw + stage * QP_TILE_B);
        float4* dst = out4 + t * QP_TILE_F4;
#pragma unroll
        for (int k = 0; k < QP_TILE_F4 / QP_THREADS; k++) {   // 4 float4 per thread
            float4 v = src[tid + k * QP_THREADS];             // conflict-free LDS.128
            __stcs(dst + tid + k * QP_THREADS, eval4(v, ca2, cb2, bb2));
        }
        __syncthreads();  // all consumers done with this stage before refill

        long long tn = t + (long long)QP_STAGES * gridDim.x;
        if (tid == 0 && tn < ntiles) {
            uint32_t mb = mbar_base + 8 * stage;
            mbar_expect_tx(mb, QP_TILE_B);
            cp_bulk_g2s(data_base + stage * QP_TILE_B,
                        x + tn * (QP_TILE_F4 * 4), QP_TILE_B, mb);
        }
        if (++stage == QP_STAGES) { stage = 0; phase ^= 1; }
    }

    // Remainder elements (n not a multiple of tile size) — simple grid-stride
    long long rem_start = (long long)ntiles * (QP_TILE_F4 * 4);
    for (long long i = rem_start + (long long)blockIdx.x * QP_THREADS + tid;
         i < n; i += (long long)gridDim.x * QP_THREADS) {
        float s, c;
        __sincosf(__ldcs(x + i), &s, &c);
        float caf, cbf, bbf, dum;
        unpack2(ca2, caf, dum); unpack2(cb2, cbf, dum); unpack2(bb2, bbf, dum);
        __stcs(out + i, fmaf(caf, c, fmaf(cbf, s, bbf)));
    }
}

extern "C" void kernel_launch(void* const* d_in, const int* in_sizes, int n_in,
                              void* d_out, int out_size) {
    const float* x       = (const float*)d_in[0];
    const float* weights = (const float*)d_in[1];
    const float* a       = (const float*)d_in[2];
    const float* b       = (const float*)d_in[3];
    float* out = (float*)d_out;

    int n = in_sizes[0];
    int ntiles = n / (QP_TILE_F4 * 4);   // 4096-float tiles

    cudaFuncSetAttribute(qpinn_tma, cudaFuncAttributeMaxDynamicSharedMemorySize,
                         QP_SMEM_SIZE);

    // 3 CTAs/SM (64KB smem each -> 192KB/SM staged), single persistent wave.
    int blocks = 148 * 3;
    if (ntiles > 0 && ntiles < blocks) blocks = ntiles;
    if (ntiles == 0) blocks = 1;

    qpinn_tma<<<blocks, QP_THREADS, QP_SMEM_SIZE>>>(x, out, ntiles, n,
                                                    weights, a, b);
}

// round 13
// speedup vs baseline: 1.1168x; 1.0135x over previous
#include <cuda_runtime.h>
#include <cstdint>

#define QP_THREADS   256
#define QP_TILE_F4   1024                 // float4 per tile = 16KB
#define QP_TILE_B    (QP_TILE_F4 * 16)    // 16384 bytes
#define QP_STAGES    3
#define QP_SMEM_SIZE (QP_STAGES * QP_TILE_B + QP_STAGES * 8)   // 48KB + barriers

// ---- PTX helpers ----
__device__ __forceinline__ uint32_t smem_u32(const void* p) {
    uint32_t a;
    asm("{ .reg .u64 t; cvta.to.shared.u64 t, %1; cvt.u32.u64 %0, t; }"
        : "=r"(a) : "l"(p));
    return a;
}
__device__ __forceinline__ void mbar_init(uint32_t mb, uint32_t cnt) {
    asm volatile("mbarrier.init.shared.b64 [%0], %1;" :: "r"(mb), "r"(cnt) : "memory");
}
__device__ __forceinline__ void mbar_expect_tx(uint32_t mb, uint32_t bytes) {
    asm volatile("mbarrier.arrive.expect_tx.shared.b64 _, [%0], %1;"
                 :: "r"(mb), "r"(bytes) : "memory");
}
__device__ __forceinline__ void mbar_wait(uint32_t mb, uint32_t parity) {
    uint32_t done;
    asm volatile(
        "{\n\t.reg .pred p;\n\t"
        "mbarrier.try_wait.parity.acquire.cta.shared::cta.b64 p, [%1], %2;\n\t"
        "selp.b32 %0, 1, 0, p;\n\t}"
        : "=r"(done) : "r"(mb), "r"(parity) : "memory");
    if (!done) {
        asm volatile(
            "{\n\t.reg .pred P1;\n\t"
            "WAIT_LOOP_%=:\n\t"
            "mbarrier.try_wait.parity.acquire.cta.shared::cta.b64 P1, [%0], %1, 0x989680;\n\t"
            "@P1 bra.uni WAIT_DONE_%=;\n\t"
            "bra.uni WAIT_LOOP_%=;\n\t"
            "WAIT_DONE_%=:\n\t}"
            :: "r"(mb), "r"(parity) : "memory");
    }
}
// 1D bulk async copy global->shared::cta, completion via mbarrier tx-bytes
__device__ __forceinline__ void cp_bulk_g2s(uint32_t dst, const void* src,
                                            uint32_t bytes, uint32_t mb) {
    asm volatile(
        "cp.async.bulk.shared::cta.global.mbarrier::complete_tx::bytes [%0], [%1], %2, [%3];"
        :: "r"(dst), "l"(src), "r"(bytes), "r"(mb) : "memory");
}

// ---- packed f32x2 FFMA2 helpers ----
__device__ __forceinline__ unsigned long long pack2(float lo, float hi) {
    unsigned long long r;
    asm("mov.b64 %0, {%1, %2};" : "=l"(r) : "f"(lo), "f"(hi));
    return r;
}
__device__ __forceinline__ void unpack2(unsigned long long v, float& lo, float& hi) {
    asm("mov.b64 {%0, %1}, %2;" : "=f"(lo), "=f"(hi) : "l"(v));
}
__device__ __forceinline__ unsigned long long ffma2(unsigned long long a,
                                                    unsigned long long b,
                                                    unsigned long long c) {
    unsigned long long r;
    asm("fma.rn.f32x2 %0, %1, %2, %3;" : "=l"(r) : "l"(a), "l"(b), "l"(c));
    return r;
}

// ---- circuit collapse (MUFU-cheap, per thread) ----
struct C2 { float r, i; };
__device__ __forceinline__ C2 cmul(C2 a, C2 b) {
    return { a.r * b.r - a.i * b.i, a.r * b.i + a.i * b.r };
}
__device__ __forceinline__ C2 cadd(C2 a, C2 b) { return { a.r + b.r, a.i + b.i }; }
__device__ __forceinline__ void mm2(const C2 A[2][2], const C2 B[2][2], C2 O[2][2]) {
#pragma unroll
    for (int r = 0; r < 2; r++)
#pragma unroll
        for (int c = 0; c < 2; c++)
            O[r][c] = cadd(cmul(A[r][0], B[0][c]), cmul(A[r][1], B[1][c]));
}
__device__ __forceinline__ void layer_unitary(float w0, float w1, float w2, C2 U[2][2]) {
    float c0, s0, c1, s1, c2, s2;
    __sincosf(0.5f * w0, &s0, &c0);
    __sincosf(0.5f * w1, &s1, &c1);
    __sincosf(0.5f * w2, &s2, &c2);
    C2 rx[2][2] = { { {c0, 0.f}, {0.f, -s0} }, { {0.f, -s0}, {c0, 0.f} } };
    C2 ry[2][2] = { { {c1, 0.f}, {-s1, 0.f} }, { {s1, 0.f}, {c1, 0.f} } };
    C2 rz[2][2] = { { {c2, -s2}, {0.f, 0.f} }, { {0.f, 0.f}, {c2, s2} } };
    C2 t[2][2];
    mm2(ry, rx, t);
    mm2(rz, t, U);
}
__device__ __forceinline__ void compute_coefs(const float* __restrict__ weights,
                                              const float* __restrict__ a,
                                              const float* __restrict__ b,
                                              float& ca, float& cb, float& bb) {
    C2 U0[2][2], U1[2][2], U[2][2];
    layer_unitary(__ldg(weights + 0), __ldg(weights + 1), __ldg(weights + 2), U0);
    layer_unitary(__ldg(weights + 3), __ldg(weights + 4), __ldg(weights + 5), U1);
    mm2(U1, U0, U);
    float alpha = (U[0][0].r * U[0][0].r + U[0][0].i * U[0][0].i)
                - (U[1][0].r * U[1][0].r + U[1][0].i * U[1][0].i);
    float beta  = (U[0][0].r * U[0][1].r + U[0][0].i * U[0][1].i)
                - (U[1][0].r * U[1][1].r + U[1][0].i * U[1][1].i);
    float av = __ldg(a);
    ca = av * alpha;
    cb = av * beta;
    bb = __ldg(b);
}
__device__ __forceinline__ float4 eval4(float4 v, unsigned long long ca2,
                                        unsigned long long cb2, unsigned long long bb2) {
    float sx, cx, sy, cy, sz, cz, sw, cw;
    __sincosf(v.x, &sx, &cx);
    __sincosf(v.y, &sy, &cy);
    __sincosf(v.z, &sz, &cz);
    __sincosf(v.w, &sw, &cw);
    unsigned long long r01 = ffma2(ca2, pack2(cx, cy), ffma2(cb2, pack2(sx, sy), bb2));
    unsigned long long r23 = ffma2(ca2, pack2(cz, cw), ffma2(cb2, pack2(sz, sw), bb2));
    float4 o;
    unpack2(r01, o.x, o.y);
    unpack2(r23, o.z, o.w);
    return o;
}

__global__ void __launch_bounds__(QP_THREADS, 4)
qpinn_tma(const float* __restrict__ x, float* __restrict__ out, int ntiles, int n,
          const float* __restrict__ weights,
          const float* __restrict__ a, const float* __restrict__ b) {
    extern __shared__ __align__(128) unsigned char smem_raw[];

    float ca, cb, bb;
    compute_coefs(weights, a, b, ca, cb, bb);
    const unsigned long long ca2 = pack2(ca, ca);
    const unsigned long long cb2 = pack2(cb, cb);
    const unsigned long long bb2 = pack2(bb, bb);

    const int tid = threadIdx.x;
    const uint32_t smem_base = smem_u32(smem_raw);
    const uint32_t data_base = smem_base;
    const uint32_t mbar_base = smem_base + QP_STAGES * QP_TILE_B;

    if (tid == 0) {
#pragma unroll
        for (int s = 0; s < QP_STAGES; s++) mbar_init(mbar_base + 8 * s, 1);
    }
    __syncthreads();

    // Prologue: fill pipeline for this block's first tiles (block-cyclic tiles)
    if (tid == 0) {
        int issued = 0;
        for (long long t = blockIdx.x; t < ntiles && issued < QP_STAGES;
             t += gridDim.x, issued++) {
            uint32_t mb = mbar_base + 8 * issued;
            mbar_expect_tx(mb, QP_TILE_B);
            cp_bulk_g2s(data_base + issued * QP_TILE_B,
                        x + t * (QP_TILE_F4 * 4), QP_TILE_B, mb);
        }
    }

    float4* __restrict__ out4 = (float4*)out;
    int stage = 0, phase = 0;
    for (long long t = blockIdx.x; t < ntiles; t += gridDim.x) {
        mbar_wait(mbar_base + 8 * stage, phase);

        const float4* src = (const float4*)(smem_raw + stage * QP_TILE_B);
        float4* dst = out4 + t * QP_TILE_F4;
#pragma unroll
        for (int k = 0; k < QP_TILE_F4 / QP_THREADS; k++) {   // 4 float4 per thread
            float4 v = src[tid + k * QP_THREADS];             // conflict-free LDS.128
            __stcs(dst + tid + k * QP_THREADS, eval4(v, ca2, cb2, bb2));
        }
        __syncthreads();  // all consumers done with this stage before refill

        long long tn = t + (long long)QP_STAGES * gridDim.x;
        if (tid == 0 && tn < ntiles) {
            uint32_t mb = mbar_base + 8 * stage;
            mbar_expect_tx(mb, QP_TILE_B);
            cp_bulk_g2s(data_base + stage * QP_TILE_B,
                        x + tn * (QP_TILE_F4 * 4), QP_TILE_B, mb);
        }
        if (++stage == QP_STAGES) { stage = 0; phase ^= 1; }
    }

    // Remainder elements (n not a multiple of tile size) — simple grid-stride
    long long rem_start = (long long)ntiles * (QP_TILE_F4 * 4);
    for (long long i = rem_start + (long long)blockIdx.x * QP_THREADS + tid;
         i < n; i += (long long)gridDim.x * QP_THREADS) {
        float s, c;
        __sincosf(__ldcs(x + i), &s, &c);
        float caf, cbf, bbf, dum;
        unpack2(ca2, caf, dum); unpack2(cb2, cbf, dum); unpack2(bb2, bbf, dum);
        __stcs(out + i, fmaf(caf, c, fmaf(cbf, s, bbf)));
    }
}

extern "C" void kernel_launch(void* const* d_in, const int* in_sizes, int n_in,
                              void* d_out, int out_size) {
    const float* x       = (const float*)d_in[0];
    const float* weights = (const float*)d_in[1];
    const float* a       = (const float*)d_in[2];
    const float* b       = (const float*)d_in[3];
    float* out = (float*)d_out;

    int n = in_sizes[0];
    int ntiles = n / (QP_TILE_F4 * 4);   // 4096-float tiles

    cudaFuncSetAttribute(qpinn_tma, cudaFuncAttributeMaxDynamicSharedMemorySize,
                         QP_SMEM_SIZE);

    // 4 CTAs/SM (48KB smem each -> 192KB/SM staged), single persistent wave.
    int blocks = 148 * 4;
    if (ntiles > 0 && ntiles < blocks) blocks = ntiles;
    if (ntiles == 0) blocks = 1;

    qpinn_tma<<<blocks, QP_THREADS, QP_SMEM_SIZE>>>(x, out, ntiles, n,
                                                    weights, a, b);
}